// round 2
// baseline (speedup 1.0000x reference)
#include <cuda_runtime.h>
#include <cstdint>

#define D 64
#define MAXN 100000

// Scratch (device globals — no allocation allowed)
__device__ float g_agg[MAXN * D];   // (1+eps)*x + sum_agg ; later reused as t2
__device__ float g_t1[MAXN * D];    // output of first Linear
__device__ float g_stats[256];      // sum1[64], sq1[64], sum2[64], sq2[64]

// ---------------------------------------------------------------------------
// K0: agg = (1+eps)*x ; zero stats accumulators
// ---------------------------------------------------------------------------
__global__ __launch_bounds__(256) void k_init(const float* __restrict__ x,
                                              const float* __restrict__ epsp,
                                              float* __restrict__ agg, int n4) {
    int i = blockIdx.x * 256 + threadIdx.x;
    if (blockIdx.x == 0 && threadIdx.x < 256) g_stats[threadIdx.x] = 0.f;
    if (i >= n4) return;
    float s = 1.0f + epsp[0];
    float4 v = ((const float4*)x)[i];
    v.x *= s; v.y *= s; v.z *= s; v.w *= s;
    ((float4*)agg)[i] = v;
}

// ---------------------------------------------------------------------------
// K1: scatter-add  agg[dst] += x[src]   (16 threads per edge, v4 reductions)
// edge_index is INT32 (jax x64 disabled downgrades int64 -> int32)
// ---------------------------------------------------------------------------
__global__ __launch_bounds__(256) void k_scatter(const float* __restrict__ x,
                                                 const int* __restrict__ ei,
                                                 float* __restrict__ agg, int E) {
    long long idx = (long long)blockIdx.x * 256 + threadIdx.x;
    long long e = idx >> 4;
    int q = (int)(idx & 15);
    if (e >= E) return;
    int src = ei[e];
    int dst = ei[(long long)E + e];
    float4 v = ((const float4*)x)[(size_t)src * 16 + q];
    float* p = agg + (size_t)dst * 64 + q * 4;
    asm volatile("red.global.add.v4.f32 [%0], {%1, %2, %3, %4};"
                 :: "l"(p), "f"(v.x), "f"(v.y), "f"(v.z), "f"(v.w)
                 : "memory");
}

// ---------------------------------------------------------------------------
// K2/K3: out = [maybe BN+ReLU](in) @ W + b ; accumulate column sum/sumsq
// Block: 256 threads, 64-row tile. thread (t = tid&15 -> 4 cols, r = tid>>4 -> 4 rows)
// ---------------------------------------------------------------------------
__global__ __launch_bounds__(256) void k_gemm_bn(
    const float* __restrict__ in, const float* __restrict__ W,
    const float* __restrict__ b, float* __restrict__ out,
    float* __restrict__ statsOut,            // [0..63]=sum, [64..127]=sumsq
    const float* __restrict__ statsIn,       // sum/sq of the *input* (or null)
    const float* __restrict__ gamma, const float* __restrict__ beta,
    int N, int applyBNin)
{
    __shared__ float Xs[64 * 68];
    __shared__ float Ws[64 * 64];
    __shared__ float Bs[64];
    __shared__ float SC[64];
    __shared__ float SH[64];
    __shared__ float red[16 * 64];

    const int tid = threadIdx.x;
    const int t = tid & 15;       // column group (4 cols)
    const int r = tid >> 4;       // row group (4 rows)
    const int row0 = blockIdx.x * 64;

    // Load W (64x64) and bias
    #pragma unroll
    for (int i = 0; i < 4; i++) {
        int lin = tid + i * 256;
        ((float4*)Ws)[lin] = ((const float4*)W)[lin];
    }
    if (tid < 64) {
        Bs[tid] = b[tid];
        if (applyBNin) {
            float invN = 1.0f / (float)N;
            float mean = statsIn[tid] * invN;
            float var  = statsIn[64 + tid] * invN - mean * mean;
            float sc = gamma[tid] * rsqrtf(var + 1e-5f);
            SC[tid] = sc;
            SH[tid] = beta[tid] - mean * sc;
        }
    }
    __syncthreads();

    // Stage 64 input rows (apply BN+ReLU on the fly if requested)
    #pragma unroll
    for (int i = 0; i < 4; i++) {
        int lin = tid + i * 256;          // float4 index within tile
        int row = lin >> 4;
        int c4 = lin & 15;
        float4 v = make_float4(0.f, 0.f, 0.f, 0.f);
        int gr = row0 + row;
        if (gr < N) v = ((const float4*)in)[(size_t)gr * 16 + c4];
        if (applyBNin) {
            int c = c4 * 4;
            v.x = fmaxf(fmaf(v.x, SC[c + 0], SH[c + 0]), 0.f);
            v.y = fmaxf(fmaf(v.y, SC[c + 1], SH[c + 1]), 0.f);
            v.z = fmaxf(fmaf(v.z, SC[c + 2], SH[c + 2]), 0.f);
            v.w = fmaxf(fmaf(v.w, SC[c + 3], SH[c + 3]), 0.f);
        }
        *(float4*)&Xs[row * 68 + c4 * 4] = v;
    }
    __syncthreads();

    // Register-tiled GEMM: 4 rows x 4 cols per thread
    float4 a0 = make_float4(0.f,0.f,0.f,0.f);
    float4 a1 = a0, a2 = a0, a3 = a0;
    const int xb = (r * 4) * 68;
    #pragma unroll
    for (int k = 0; k < 64; k++) {
        float4 w = *(const float4*)&Ws[k * 64 + t * 4];
        float x0 = Xs[xb + k];
        float x1 = Xs[xb + 68 + k];
        float x2 = Xs[xb + 136 + k];
        float x3 = Xs[xb + 204 + k];
        a0.x = fmaf(x0, w.x, a0.x); a0.y = fmaf(x0, w.y, a0.y);
        a0.z = fmaf(x0, w.z, a0.z); a0.w = fmaf(x0, w.w, a0.w);
        a1.x = fmaf(x1, w.x, a1.x); a1.y = fmaf(x1, w.y, a1.y);
        a1.z = fmaf(x1, w.z, a1.z); a1.w = fmaf(x1, w.w, a1.w);
        a2.x = fmaf(x2, w.x, a2.x); a2.y = fmaf(x2, w.y, a2.y);
        a2.z = fmaf(x2, w.z, a2.z); a2.w = fmaf(x2, w.w, a2.w);
        a3.x = fmaf(x3, w.x, a3.x); a3.y = fmaf(x3, w.y, a3.y);
        a3.z = fmaf(x3, w.z, a3.z); a3.w = fmaf(x3, w.w, a3.w);
    }
    float4 bb = *(const float4*)&Bs[t * 4];
    a0.x += bb.x; a0.y += bb.y; a0.z += bb.z; a0.w += bb.w;
    a1.x += bb.x; a1.y += bb.y; a1.z += bb.z; a1.w += bb.w;
    a2.x += bb.x; a2.y += bb.y; a2.z += bb.z; a2.w += bb.w;
    a3.x += bb.x; a3.y += bb.y; a3.z += bb.z; a3.w += bb.w;

    // Store + local stats
    float4 ls = make_float4(0.f,0.f,0.f,0.f);
    float4 lq = ls;
    float4 acc[4] = {a0, a1, a2, a3};
    #pragma unroll
    for (int j = 0; j < 4; j++) {
        int row = row0 + r * 4 + j;
        if (row < N) {
            *(float4*)&out[(size_t)row * 64 + t * 4] = acc[j];
            ls.x += acc[j].x; ls.y += acc[j].y; ls.z += acc[j].z; ls.w += acc[j].w;
            lq.x += acc[j].x * acc[j].x; lq.y += acc[j].y * acc[j].y;
            lq.z += acc[j].z * acc[j].z; lq.w += acc[j].w * acc[j].w;
        }
    }

    // Block reduction of stats, then atomic into global accumulators
    __syncthreads();
    *(float4*)&red[r * 64 + t * 4] = ls;
    __syncthreads();
    if (tid < 64) {
        float s = 0.f;
        #pragma unroll
        for (int rr = 0; rr < 16; rr++) s += red[rr * 64 + tid];
        atomicAdd(&statsOut[tid], s);
    }
    __syncthreads();
    *(float4*)&red[r * 64 + t * 4] = lq;
    __syncthreads();
    if (tid < 64) {
        float s = 0.f;
        #pragma unroll
        for (int rr = 0; rr < 16; rr++) s += red[rr * 64 + tid];
        atomicAdd(&statsOut[64 + tid], s);
    }
}

// ---------------------------------------------------------------------------
// K4: out = x + relu(BN(t2))
// ---------------------------------------------------------------------------
__global__ __launch_bounds__(256) void k_final(const float* __restrict__ x,
                                               const float* __restrict__ t2,
                                               const float* __restrict__ statsIn,
                                               const float* __restrict__ gamma,
                                               const float* __restrict__ beta,
                                               float* __restrict__ out, int N) {
    __shared__ float SC[64];
    __shared__ float SH[64];
    int tid = threadIdx.x;
    if (tid < 64) {
        float invN = 1.0f / (float)N;
        float mean = statsIn[tid] * invN;
        float var  = statsIn[64 + tid] * invN - mean * mean;
        float sc = gamma[tid] * rsqrtf(var + 1e-5f);
        SC[tid] = sc;
        SH[tid] = beta[tid] - mean * sc;
    }
    __syncthreads();
    int n4 = N * 16;
    for (int i = blockIdx.x * 256 + tid; i < n4; i += gridDim.x * 256) {
        int c = (i & 15) * 4;
        float4 v = ((const float4*)t2)[i];
        float4 xv = ((const float4*)x)[i];
        float4 o;
        o.x = xv.x + fmaxf(fmaf(v.x, SC[c + 0], SH[c + 0]), 0.f);
        o.y = xv.y + fmaxf(fmaf(v.y, SC[c + 1], SH[c + 1]), 0.f);
        o.z = xv.z + fmaxf(fmaf(v.z, SC[c + 2], SH[c + 2]), 0.f);
        o.w = xv.w + fmaxf(fmaf(v.w, SC[c + 3], SH[c + 3]), 0.f);
        ((float4*)out)[i] = o;
    }
}

// ---------------------------------------------------------------------------
extern "C" void kernel_launch(void* const* d_in, const int* in_sizes, int n_in,
                              void* d_out, int out_size) {
    const float* x    = (const float*)d_in[0];
    const int*   ei   = (const int*)d_in[1];      // int32! (jax x64 disabled)
    const float* eps  = (const float*)d_in[2];
    const float* W1   = (const float*)d_in[3];
    const float* b1   = (const float*)d_in[4];
    const float* g1   = (const float*)d_in[5];
    const float* beta1= (const float*)d_in[6];
    const float* W2   = (const float*)d_in[7];
    const float* b2   = (const float*)d_in[8];
    const float* gh   = (const float*)d_in[9];
    const float* betah= (const float*)d_in[10];
    float* out = (float*)d_out;

    int N = in_sizes[0] / D;
    int E = in_sizes[1] / 2;
    if (N > MAXN) N = MAXN;   // scratch bound (problem is fixed at N=100000)

    float* agg;   cudaGetSymbolAddress((void**)&agg, g_agg);
    float* t1;    cudaGetSymbolAddress((void**)&t1, g_t1);
    float* stats; cudaGetSymbolAddress((void**)&stats, g_stats);

    int n4 = N * 16;
    int initBlocks = (n4 + 255) / 256;
    k_init<<<initBlocks, 256>>>(x, eps, agg, n4);

    long long scatterThreads = (long long)E * 16;
    int scatterBlocks = (int)((scatterThreads + 255) / 256);
    k_scatter<<<scatterBlocks, 256>>>(x, ei, agg, E);

    int gemmBlocks = (N + 63) / 64;
    // t1 = agg @ W1 + b1 ; stats1
    k_gemm_bn<<<gemmBlocks, 256>>>(agg, W1, b1, t1, stats, nullptr, nullptr, nullptr, N, 0);
    // t2 = relu(BN1(t1)) @ W2 + b2 ; stats2   (t2 reuses g_agg)
    k_gemm_bn<<<gemmBlocks, 256>>>(t1, W2, b2, agg, stats + 128, stats, g1, beta1, N, 1);
    // out = x + relu(BN2(t2))
    k_final<<<initBlocks, 256>>>(x, agg, stats + 128, gh, betah, out, N);
}